// round 13
// baseline (speedup 1.0000x reference)
#include <cuda_runtime.h>
#include <cuda_fp16.h>
#include <math.h>

#define NMAX 50000
#define EMAX 1600000
#define FIN 16
#define TT 12
#define HID 32
#define FT (FIN*TT)   // 192 values per node
#define SB 512        // scan block size
#define PADH 200      // padded halves per node row in smem (conflict-free)

// ---------------- scratch (static device globals; no allocation) ----------------
__device__ int    g_cnt[NMAX];                    // in-degree counts; zeroed by k_fill each run
__device__ int    g_rowptr[NMAX + 1];             // CSR row pointers
__device__ int    g_cur[NMAX];                    // fill cursors
__device__ int2   g_sw[EMAX];                     // CSR payload: {src, bits(norm weight)}
__device__ int    g_part[256];                    // scan partials
__device__ float  g_dis[NMAX];                    // rsqrt(degree incl. self-loop)
__device__ __half g_xh[(size_t)NMAX * FT];        // fp16 features, t-major [N][T][F]
__device__ float  g_A[3 * FIN * HID];             // folded W_g @ L_g_top
__device__ float  g_c[3 * HID];                   // folded biases
__device__ float  g_probs[TT];                    // softmax(att)
__device__ float  g_hsum[HID];                    // sum over nodes of relu(Hacc); zeroed by k_final
// prebuilt GRU HMMA fragments, lane-indexed for coalesced loads
__device__ uint4  g_fzr[12][32];                  // z,r B-fragments
__device__ uint4  g_fh[6][32];                    // candidate B-fragments
__device__ float4 g_fzc[4][32];                   // z,r bias fragments
__device__ float4 g_fhc[2][32];                   // candidate bias fragments

// ---------------- helpers ----------------
__device__ __forceinline__ float sigf(float x) {
    return __fdividef(1.0f, 1.0f + __expf(-x));
}
__device__ __forceinline__ float tanhfast(float x) {
    return fmaf(2.0f, __fdividef(1.0f, 1.0f + __expf(-2.0f * x)), -1.0f);
}
union F4H2 { float4 f4; __half2 h2[4]; };

typedef unsigned long long u64;
__device__ __forceinline__ u64 pk2(float x, float y) {
    u64 r; asm("mov.b64 %0, {%1,%2};" : "=l"(r) : "f"(x), "f"(y)); return r;
}
__device__ __forceinline__ u64 fma2(u64 a, u64 b, u64 c) {
    u64 d; asm("fma.rn.f32x2 %0, %1, %2, %3;" : "=l"(d) : "l"(a), "l"(b), "l"(c)); return d;
}
__device__ __forceinline__ void up2(u64 v, float& x, float& y) {
    asm("mov.b64 {%0,%1}, %2;" : "=f"(x), "=f"(y) : "l"(v));
}

__device__ __forceinline__ unsigned h2pack(float lo, float hi) {
    __half2 h = __floats2half2_rn(lo, hi);
    return *reinterpret_cast<unsigned*>(&h);
}

// m16n8k16 row.col f16 inputs, f32 accum (C += A*B)
__device__ __forceinline__ void mma16816(float* c, const unsigned* a, const unsigned* b) {
    asm volatile(
        "mma.sync.aligned.m16n8k16.row.col.f32.f16.f16.f32 "
        "{%0,%1,%2,%3}, {%4,%5,%6,%7}, {%8,%9}, {%0,%1,%2,%3};"
        : "+f"(c[0]), "+f"(c[1]), "+f"(c[2]), "+f"(c[3])
        : "r"(a[0]), "r"(a[1]), "r"(a[2]), "r"(a[3]), "r"(b[0]), "r"(b[1]));
}

__device__ __forceinline__ void red_add(int* p) {
    asm volatile("red.global.add.s32 [%0], %1;" :: "l"(p), "r"(1) : "memory");
}

// fragment source values (folded top + raw bottom halves of L matrices)
__device__ __forceinline__ float wzr_at(int k, int n,
                                        const float* LzW, const float* LrW) {
    int g = n >> 5, col = n & 31;
    if (k < 16) return g_A[(g * 16 + k) * 32 + col];
    const float* L = g ? LrW : LzW;
    return L[(k + 16) * 32 + col];          // bottom rows 32..63 of L
}
__device__ __forceinline__ float wh_at(int k, int n, const float* LhW) {
    if (k < 16) return g_A[(2 * 16 + k) * 32 + n];
    return LhW[(k + 16) * 32 + n];
}

// =======================================================================
// k_pre: edge-count + fp16 transpose (coalesced float4 writes) +
//        (block 0) weight fold + softmax + HMMA fragment prebuild
// grid = (N+3)/4 = 12500 blocks of 256
// =======================================================================
__global__ void __launch_bounds__(256)
k_pre(const float* __restrict__ x, const int* __restrict__ ei,
      const float* __restrict__ Wz, const float* __restrict__ bz,
      const float* __restrict__ Wr, const float* __restrict__ br,
      const float* __restrict__ Wh, const float* __restrict__ bh,
      const float* __restrict__ LzW, const float* __restrict__ Lzb,
      const float* __restrict__ LrW, const float* __restrict__ Lrb,
      const float* __restrict__ LhW, const float* __restrict__ Lhb,
      const float* __restrict__ att, int N, int E) {
    __shared__ float sx[4 * FT];
    int tid = threadIdx.x;

    // --- edge-count (fire-and-forget) ---
    int gt = blockIdx.x * 256 + tid;
    if (gt < E) red_add(&g_cnt[__ldg(&ei[E + gt])]);

    // --- transpose: 4 nodes/block, [F][T] f32 -> [T][F] f16, float4 writes ---
    size_t base = (size_t)blockIdx.x * 4 * FT;
    size_t lim  = (size_t)N * FT;
    const float4* x4 = (const float4*)(x + base);
    int nvalid = (int)min((size_t)(4 * FT), lim - base);
    #pragma unroll
    for (int i = tid; i < FT; i += 256) {       // 192 float4s
        if (i * 4 < nvalid) ((float4*)sx)[i] = x4[i];
    }
    __syncthreads();
    if (tid < 96) {                              // 4 nodes x 24 float4 outputs
        int nn  = tid / 24;
        int rem = tid % 24;                      // float4 index within node
        int t = rem >> 1, q = rem & 1;           // q: f-half (0..7 or 8..15)
        int node = blockIdx.x * 4 + nn;
        if (node < N) {
            const float* s = sx + nn * FT + t;   // s[f*TT] pattern
            F4H2 st;
            #pragma unroll
            for (int h = 0; h < 4; h++) {
                int f = q * 8 + 2 * h;
                st.h2[h] = __floats2half2_rn(s[f * TT], s[(f + 1) * TT]);
            }
            ((float4*)(g_xh + (size_t)node * FT))[rem] = st.f4;
        }
    }

    // --- block 0: full fold + softmax + fragment build ---
    if (blockIdx.x == 0) {
        const float* W[3]  = {Wz, Wr, Wh};
        const float* L[3]  = {LzW, LrW, LhW};
        const float* bb[3] = {bz, br, bh};
        const float* Lb[3] = {Lzb, Lrb, Lhb};
        #pragma unroll
        for (int rep = 0; rep < 2; rep++) {
            int id = tid + rep * 256;            // 512 (f,j) pairs
            int f = id >> 5, j = id & 31;
            #pragma unroll
            for (int g = 0; g < 3; g++) {
                float s = 0.0f;
                #pragma unroll
                for (int k = 0; k < HID; k++)
                    s = fmaf(__ldg(&W[g][f * HID + k]), __ldg(&L[g][k * HID + j]), s);
                g_A[(g * FIN + f) * HID + j] = s;
            }
        }
        if (tid < 3 * HID) {
            int g = tid >> 5, jj = tid & 31;
            float s = __ldg(&Lb[g][jj]);
            #pragma unroll
            for (int k = 0; k < HID; k++)
                s = fmaf(__ldg(&bb[g][k]), __ldg(&L[g][k * HID + jj]), s);
            g_c[g * HID + jj] = s;
        }
        if (tid >= 96 && tid < 128) {            // softmax (warp 3)
            int l = tid & 31;
            float v = (l < TT) ? __ldg(&att[l]) : -1e30f;
            float m = v;
            #pragma unroll
            for (int o = 16; o; o >>= 1) m = fmaxf(m, __shfl_xor_sync(0xffffffffu, m, o));
            float e = (l < TT) ? __expf(v - m) : 0.0f;
            float s = e;
            #pragma unroll
            for (int o = 16; o; o >>= 1) s += __shfl_xor_sync(0xffffffffu, s, o);
            if (l < TT) g_probs[l] = e * __fdividef(1.0f, s);
        }
        __syncthreads();
        if (tid < 32) {                          // fragment build (warp 0)
            int l = tid;
            int qr = l >> 2, qc = l & 3;
            #pragma unroll
            for (int s = 0; s < 3; s++) {
                int k0 = 16 * s + 2 * qc;
                #pragma unroll
                for (int jj = 0; jj < 4; jj++) {
                    int j0 = 2 * jj;
                    uint4 v;
                    v.x = h2pack(wzr_at(k0,     8 * j0 + qr, LzW, LrW), wzr_at(k0 + 1, 8 * j0 + qr, LzW, LrW));
                    v.y = h2pack(wzr_at(k0 + 8, 8 * j0 + qr, LzW, LrW), wzr_at(k0 + 9, 8 * j0 + qr, LzW, LrW));
                    v.z = h2pack(wzr_at(k0,     8 * (j0 + 1) + qr, LzW, LrW), wzr_at(k0 + 1, 8 * (j0 + 1) + qr, LzW, LrW));
                    v.w = h2pack(wzr_at(k0 + 8, 8 * (j0 + 1) + qr, LzW, LrW), wzr_at(k0 + 9, 8 * (j0 + 1) + qr, LzW, LrW));
                    g_fzr[s * 4 + jj][l] = v;
                }
                #pragma unroll
                for (int jj = 0; jj < 2; jj++) {
                    int j0 = 2 * jj;
                    uint4 v;
                    v.x = h2pack(wh_at(k0,     8 * j0 + qr, LhW), wh_at(k0 + 1, 8 * j0 + qr, LhW));
                    v.y = h2pack(wh_at(k0 + 8, 8 * j0 + qr, LhW), wh_at(k0 + 9, 8 * j0 + qr, LhW));
                    v.z = h2pack(wh_at(k0,     8 * (j0 + 1) + qr, LhW), wh_at(k0 + 1, 8 * (j0 + 1) + qr, LhW));
                    v.w = h2pack(wh_at(k0 + 8, 8 * (j0 + 1) + qr, LhW), wh_at(k0 + 9, 8 * (j0 + 1) + qr, LhW));
                    g_fh[s * 2 + jj][l] = v;
                }
            }
            #pragma unroll
            for (int i = 0; i < 4; i++) {
                int j0 = 2 * i;
                float4 v;
                v.x = g_c[8 * j0 + 2 * qc];       v.y = g_c[8 * j0 + 2 * qc + 1];
                v.z = g_c[8 * (j0 + 1) + 2 * qc]; v.w = g_c[8 * (j0 + 1) + 2 * qc + 1];
                g_fzc[i][l] = v;
            }
            #pragma unroll
            for (int i = 0; i < 2; i++) {
                int j0 = 2 * i;
                float4 v;
                v.x = g_c[64 + 8 * j0 + 2 * qc];       v.y = g_c[64 + 8 * j0 + 2 * qc + 1];
                v.z = g_c[64 + 8 * (j0 + 1) + 2 * qc]; v.w = g_c[64 + 8 * (j0 + 1) + 2 * qc + 1];
                g_fhc[i][l] = v;
            }
        }
    }
}

// ---- parallel 3-phase scan ----
__global__ void k_scan_a(int N) {
    __shared__ int ws[SB / 32];
    int tid = threadIdx.x;
    int i = blockIdx.x * SB + tid;
    int v = (i < N) ? g_cnt[i] : 0;
    #pragma unroll
    for (int o = 16; o; o >>= 1) v += __shfl_xor_sync(0xffffffffu, v, o);
    if ((tid & 31) == 0) ws[tid >> 5] = v;
    __syncthreads();
    if (tid < SB / 32) {
        int w = ws[tid];
        #pragma unroll
        for (int o = 8; o; o >>= 1) w += __shfl_xor_sync(0xffffu, w, o);
        if (tid == 0) g_part[blockIdx.x] = w;
    }
}

__global__ void k_scan_b(int NB, int N, int E) {
    __shared__ int ws[4];
    int tid = threadIdx.x, lane = tid & 31, wid = tid >> 5;
    int orig = (tid < NB) ? g_part[tid] : 0;
    int v = orig;
    #pragma unroll
    for (int o = 1; o < 32; o <<= 1) {
        int t = __shfl_up_sync(0xffffffffu, v, o);
        if (lane >= o) v += t;
    }
    if (lane == 31) ws[wid] = v;
    __syncthreads();
    if (wid == 0 && lane < 4) {
        int w = ws[lane];
        #pragma unroll
        for (int o = 1; o < 4; o <<= 1) {
            int t = __shfl_up_sync(0xfu, w, o);
            if (lane >= o) w += t;
        }
        ws[lane] = w;
    }
    __syncthreads();
    int incl = v + (wid > 0 ? ws[wid - 1] : 0);
    if (tid < NB) g_part[tid] = incl - orig;     // exclusive
    if (tid == 0) g_rowptr[N] = E;
}

__global__ void k_scan_c(int N) {
    __shared__ int ws[SB / 32];
    int tid = threadIdx.x, lane = tid & 31, wid = tid >> 5;
    int i = blockIdx.x * SB + tid;
    int c = (i < N) ? g_cnt[i] : 0;
    int v = c;
    #pragma unroll
    for (int o = 1; o < 32; o <<= 1) {
        int t = __shfl_up_sync(0xffffffffu, v, o);
        if (lane >= o) v += t;
    }
    if (lane == 31) ws[wid] = v;
    __syncthreads();
    if (wid == 0 && lane < SB / 32) {
        int w = ws[lane];
        #pragma unroll
        for (int o = 1; o < SB / 32; o <<= 1) {
            int t = __shfl_up_sync((1u << (SB / 32)) - 1u, w, o);
            if (lane >= o) w += t;
        }
        ws[lane] = w;
    }
    __syncthreads();
    int excl = v - c + (wid > 0 ? ws[wid - 1] : 0) + g_part[blockIdx.x];
    if (i < N) {
        g_rowptr[i] = excl;
        g_cur[i]    = excl;
        g_dis[i]    = rsqrtf((float)(c + 1));    // +1 self-loop
    }
}

// CSR fill: 4 edges per thread with int4 loads; re-zeros g_cnt.
__global__ void k_fill(const int* __restrict__ ei, int E, int N) {
    int i = blockIdx.x * blockDim.x + threadIdx.x;
    if (i < N) g_cnt[i] = 0;
    int base = i * 4;
    if (base >= E) return;
    int s[4], d[4];
    float ws[4];
    int m;
    if ((E & 3) == 0 && base + 4 <= E) {
        m = 4;
        int4 s4 = __ldg((const int4*)ei + i);
        int4 d4 = __ldg((const int4*)(ei + E) + i);
        s[0] = s4.x; s[1] = s4.y; s[2] = s4.z; s[3] = s4.w;
        d[0] = d4.x; d[1] = d4.y; d[2] = d4.z; d[3] = d4.w;
    } else {
        m = min(4, E - base);
        for (int u = 0; u < m; u++) {
            s[u] = __ldg(&ei[base + u]);
            d[u] = __ldg(&ei[E + base + u]);
        }
    }
    #pragma unroll
    for (int u = 0; u < 4; u++)
        if (u < m) ws[u] = g_dis[s[u]] * g_dis[d[u]];
    #pragma unroll
    for (int u = 0; u < 4; u++) {
        if (u < m) {
            int p = atomicAdd(&g_cur[d[u]], 1);
            g_sw[p] = make_int2(s[u], __float_as_int(ws[u]));
        }
    }
}

// =======================================================================
// k_ggru: fused gather + tensor-core GRU. Warp = 16 nodes.
// Phase 1: warp gathers each node's 192 fp16 agg values into padded smem.
// Phase 2: HMMA GRU reads A-fragments straight from smem.
// =======================================================================
__global__ void __launch_bounds__(128)
k_ggru(int N) {
    __shared__ __half sagg[4][16][PADH];     // 25.6 KB, padded rows
    __shared__ int2  stage[4][32];
    __shared__ float sp[TT];
    __shared__ float bsum[HID];

    int tid = threadIdx.x;
    if (tid < TT) sp[tid] = g_probs[tid];
    if (tid < HID) bsum[tid] = 0.0f;
    __syncthreads();

    int lane = tid & 31;
    int wloc = tid >> 5;
    int w = blockIdx.x * 4 + wloc;
    int NW = (N + 15) / 16;
    if (w < NW) {
        int base = w * 16;
        int ln = (lane < 24) ? lane : 0;

        // ---- phase 1: gather 16 nodes into smem ----
        for (int m = 0; m < 16; m++) {
            int n = min(base + m, N - 1);
            int beg = g_rowptr[n];
            int end = g_rowptr[n + 1];
            float dd = g_dis[n];

            u64 acc2[4];
            {
                float inv = dd * dd;                   // 1/deg (self-loop)
                u64 ip = pk2(inv, inv);
                F4H2 v; v.f4 = ((const float4*)(g_xh + (size_t)n * FT))[ln];
                #pragma unroll
                for (int q = 0; q < 4; q++) {
                    float2 f = __half22float2(v.h2[q]);
                    acc2[q] = fma2(ip, pk2(f.x, f.y), pk2(0.0f, 0.0f));
                }
            }
            for (int i = beg; i < end; i += 32) {
                int j = i + lane;
                if (j < end) stage[wloc][lane] = g_sw[j];
                __syncwarp();
                int mm = min(32, end - i);
                #pragma unroll 8
                for (int u = 0; u < mm; u++) {
                    int2 sw = stage[wloc][u];
                    float ww = __int_as_float(sw.y);
                    u64 wp = pk2(ww, ww);
                    F4H2 v; v.f4 = ((const float4*)(g_xh + (size_t)sw.x * FT))[ln];
                    #pragma unroll
                    for (int q = 0; q < 4; q++) {
                        float2 f = __half22float2(v.h2[q]);
                        acc2[q] = fma2(wp, pk2(f.x, f.y), acc2[q]);
                    }
                }
                __syncwarp();
            }
            if (lane < 24) {
                F4H2 st;
                #pragma unroll
                for (int q = 0; q < 4; q++) {
                    float a0, a1;
                    up2(acc2[q], a0, a1);
                    st.h2[q] = __floats2half2_rn(a0, a1);
                }
                *(float4*)(&sagg[wloc][m][lane * 8]) = st.f4;
            }
        }
        __syncwarp();

        // ---- phase 2: tensor-core GRU ----
        int qr = lane >> 2;
        int qc = lane & 3;

        unsigned bzr[3][8][2];
        unsigned bh[3][4][2];
        float bzc[8][2], bhc[4][2];
        #pragma unroll
        for (int i = 0; i < 12; i++) {
            uint4 v = g_fzr[i][lane];
            int s = i >> 2, j0 = (i & 3) * 2;
            bzr[s][j0][0] = v.x; bzr[s][j0][1] = v.y;
            bzr[s][j0 + 1][0] = v.z; bzr[s][j0 + 1][1] = v.w;
        }
        #pragma unroll
        for (int i = 0; i < 6; i++) {
            uint4 v = g_fh[i][lane];
            int s = i >> 1, j0 = (i & 1) * 2;
            bh[s][j0][0] = v.x; bh[s][j0][1] = v.y;
            bh[s][j0 + 1][0] = v.z; bh[s][j0 + 1][1] = v.w;
        }
        #pragma unroll
        for (int i = 0; i < 4; i++) {
            float4 v = g_fzc[i][lane];
            int j0 = 2 * i;
            bzc[j0][0] = v.x; bzc[j0][1] = v.y;
            bzc[j0 + 1][0] = v.z; bzc[j0 + 1][1] = v.w;
        }
        #pragma unroll
        for (int i = 0; i < 2; i++) {
            float4 v = g_fhc[i][lane];
            int j0 = 2 * i;
            bhc[j0][0] = v.x; bhc[j0][1] = v.y;
            bhc[j0 + 1][0] = v.z; bhc[j0 + 1][1] = v.w;
        }

        const unsigned* S0 = (const unsigned*)&sagg[wloc][qr][0];      // node qr
        const unsigned* S1 = (const unsigned*)&sagg[wloc][qr + 8][0];  // node qr+8

        float H[4][4], acc[4][4];
        #pragma unroll
        for (int j = 0; j < 4; j++)
            #pragma unroll
            for (int i = 0; i < 4; i++) { H[j][i] = 0.0f; acc[j][i] = 0.0f; }

        #pragma unroll 1
        for (int t = 0; t < TT; t++) {
            float p = sp[t];
            unsigned af[4];
            af[0] = S0[t * 8 + qc];     af[1] = S1[t * 8 + qc];
            af[2] = S0[t * 8 + qc + 4]; af[3] = S1[t * 8 + qc + 4];

            unsigned hA1[4] = { h2pack(H[0][0], H[0][1]), h2pack(H[0][2], H[0][3]),
                                h2pack(H[1][0], H[1][1]), h2pack(H[1][2], H[1][3]) };
            unsigned hA2[4] = { h2pack(H[2][0], H[2][1]), h2pack(H[2][2], H[2][3]),
                                h2pack(H[3][0], H[3][1]), h2pack(H[3][2], H[3][3]) };

            // ---- z,r GEMM ----
            float Czr[8][4];
            #pragma unroll
            for (int j = 0; j < 8; j++) {
                Czr[j][0] = bzc[j][0]; Czr[j][1] = bzc[j][1];
                Czr[j][2] = bzc[j][0]; Czr[j][3] = bzc[j][1];
            }
            #pragma unroll
            for (int j = 0; j < 8; j++) {
                mma16816(Czr[j], af,  bzr[0][j]);
                mma16816(Czr[j], hA1, bzr[1][j]);
                mma16816(Czr[j], hA2, bzr[2][j]);
            }
            float Z[4][4], R[4][4];
            #pragma unroll
            for (int j = 0; j < 4; j++)
                #pragma unroll
                for (int i = 0; i < 4; i++) {
                    Z[j][i] = sigf(Czr[j][i]);
                    R[j][i] = sigf(Czr[4 + j][i]) * H[j][i];
                }

            // ---- candidate GEMM ----
            unsigned rA1[4] = { h2pack(R[0][0], R[0][1]), h2pack(R[0][2], R[0][3]),
                                h2pack(R[1][0], R[1][1]), h2pack(R[1][2], R[1][3]) };
            unsigned rA2[4] = { h2pack(R[2][0], R[2][1]), h2pack(R[2][2], R[2][3]),
                                h2pack(R[3][0], R[3][1]), h2pack(R[3][2], R[3][3]) };
            float Ch[4][4];
            #pragma unroll
            for (int j = 0; j < 4; j++) {
                Ch[j][0] = bhc[j][0]; Ch[j][1] = bhc[j][1];
                Ch[j][2] = bhc[j][0]; Ch[j][3] = bhc[j][1];
            }
            #pragma unroll
            for (int j = 0; j < 4; j++) {
                mma16816(Ch[j], af,  bh[0][j]);
                mma16816(Ch[j], rA1, bh[1][j]);
                mma16816(Ch[j], rA2, bh[2][j]);
            }
            // ---- state update ----
            #pragma unroll
            for (int j = 0; j < 4; j++)
                #pragma unroll
                for (int i = 0; i < 4; i++) {
                    float ht = tanhfast(Ch[j][i]);
                    float z = Z[j][i];
                    H[j][i] = z * H[j][i] + (1.0f - z) * ht;
                    acc[j][i] = fmaf(p, H[j][i], acc[j][i]);
                }
        }

        // ---- relu + reduce ----
        bool v0 = (base + qr)     < N;
        bool v1 = (base + qr + 8) < N;
        #pragma unroll
        for (int j = 0; j < 4; j++) {
            float a0 = acc[j][0], a1 = acc[j][1], a2 = acc[j][2], a3 = acc[j][3];
            float s0 = (v0 ? fmaxf(a0, 0.0f) : 0.0f) + (v1 ? fmaxf(a2, 0.0f) : 0.0f);
            float s1 = (v0 ? fmaxf(a1, 0.0f) : 0.0f) + (v1 ? fmaxf(a3, 0.0f) : 0.0f);
            #pragma unroll
            for (int o = 4; o < 32; o <<= 1) {
                s0 += __shfl_xor_sync(0xffffffffu, s0, o);
                s1 += __shfl_xor_sync(0xffffffffu, s1, o);
            }
            if (qr == 0) {
                atomicAdd(&bsum[8 * j + 2 * qc],     s0);
                atomicAdd(&bsum[8 * j + 2 * qc + 1], s1);
            }
        }
    }
    __syncthreads();
    if (tid < HID) atomicAdd(&g_hsum[tid], bsum[tid]);
}

// Final readout; also re-zeros g_hsum for the next replay.
__global__ void k_final(const float* __restrict__ linW, const float* __restrict__ linb,
                        float* out, int N) {
    int j = threadIdx.x;   // 32 threads
    float invN = 1.0f / (float)N;
    float h = g_hsum[j];
    g_hsum[j] = 0.0f;
    float v = h * invN * linW[j];
    #pragma unroll
    for (int o = 16; o; o >>= 1) v += __shfl_xor_sync(0xffffffffu, v, o);
    if (j == 0) {
        float r = v + linb[0];
        out[0] = r > 0.0f ? r : 0.0f;
    }
}

// ---------------- launcher ----------------
extern "C" void kernel_launch(void* const* d_in, const int* in_sizes, int n_in,
                              void* d_out, int out_size) {
    const float* x    = (const float*)d_in[0];
    const int*   ei   = (const int*)  d_in[1];
    const float* att  = (const float*)d_in[2];
    const float* Wz   = (const float*)d_in[3];
    const float* bz   = (const float*)d_in[4];
    const float* Wr   = (const float*)d_in[5];
    const float* br   = (const float*)d_in[6];
    const float* Wh   = (const float*)d_in[7];
    const float* bh   = (const float*)d_in[8];
    const float* LzW  = (const float*)d_in[9];
    const float* Lzb  = (const float*)d_in[10];
    const float* LrW  = (const float*)d_in[11];
    const float* Lrb  = (const float*)d_in[12];
    const float* LhW  = (const float*)d_in[13];
    const float* Lhb  = (const float*)d_in[14];
    const float* linW = (const float*)d_in[15];
    const float* linb = (const float*)d_in[16];

    int N = in_sizes[0] / FT;
    int E = in_sizes[1] / 2;
    int NB = (N + SB - 1) / SB;
    int NW = (N + 15) / 16;             // ggru warps (16 nodes each)
    int NQ = (E + 3) / 4;               // quad-edge fill threads

    k_pre<<<(N + 3) / 4, 256>>>(x, ei, Wz, bz, Wr, br, Wh, bh,
                                LzW, Lzb, LrW, Lrb, LhW, Lhb, att, N, E);
    k_scan_a<<<NB, SB>>>(N);
    k_scan_b<<<1, 128>>>(NB, N, E);
    k_scan_c<<<NB, SB>>>(N);
    k_fill<<<(NQ + 255) / 256, 256>>>(ei, E, N);
    k_ggru<<<(NW + 3) / 4, 128>>>(N);
    k_final<<<1, 32>>>(linW, linb, (float*)d_out, N);
}

// round 14
// speedup vs baseline: 1.2967x; 1.2967x over previous
#include <cuda_runtime.h>
#include <cuda_fp16.h>
#include <math.h>

#define NMAX 50000
#define EMAX 1600000
#define FIN 16
#define TT 12
#define HID 32
#define FT (FIN*TT)   // 192 values per node
#define SB 512        // scan block size

// ---------------- scratch (static device globals; no allocation) ----------------
__device__ int    g_cnt[NMAX];                    // in-degree counts; zeroed by k_fill each run
__device__ int    g_rowptr[NMAX + 1];             // CSR row pointers
__device__ int    g_cur[NMAX];                    // fill cursors
__device__ int2   g_sw[EMAX];                     // CSR payload: {src, bits(norm weight)}
__device__ int    g_part[256];                    // scan partials
__device__ float  g_dis[NMAX];                    // rsqrt(degree incl. self-loop)
__device__ __half g_xh[(size_t)NMAX * FT];        // fp16 features, t-major [N][T][F]
__device__ __half g_aggh[(size_t)NMAX * FT];      // aggregated features fp16, t-major
__device__ float  g_A[3 * FIN * HID];             // folded W_g @ L_g_top
__device__ float  g_c[3 * HID];                   // folded biases
__device__ float  g_probs[TT];                    // softmax(att)
__device__ float  g_hsum[HID];                    // sum over nodes of relu(Hacc); zeroed by k_final
// prebuilt GRU HMMA fragments, lane-indexed for coalesced loads
__device__ uint4  g_fzr[12][32];                  // z,r B-fragments
__device__ uint4  g_fh[6][32];                    // candidate B-fragments
__device__ float4 g_fzc[4][32];                   // z,r bias fragments
__device__ float4 g_fhc[2][32];                   // candidate bias fragments

// ---------------- helpers ----------------
__device__ __forceinline__ float sigf(float x) {
    return __fdividef(1.0f, 1.0f + __expf(-x));
}
__device__ __forceinline__ float tanhfast(float x) {
    return fmaf(2.0f, __fdividef(1.0f, 1.0f + __expf(-2.0f * x)), -1.0f);
}
union F4H2 { float4 f4; __half2 h2[4]; };

typedef unsigned long long u64;
__device__ __forceinline__ u64 pk2(float x, float y) {
    u64 r; asm("mov.b64 %0, {%1,%2};" : "=l"(r) : "f"(x), "f"(y)); return r;
}
__device__ __forceinline__ u64 fma2(u64 a, u64 b, u64 c) {
    u64 d; asm("fma.rn.f32x2 %0, %1, %2, %3;" : "=l"(d) : "l"(a), "l"(b), "l"(c)); return d;
}
__device__ __forceinline__ void up2(u64 v, float& x, float& y) {
    asm("mov.b64 {%0,%1}, %2;" : "=f"(x), "=f"(y) : "l"(v));
}

__device__ __forceinline__ unsigned h2pack(float lo, float hi) {
    __half2 h = __floats2half2_rn(lo, hi);
    return *reinterpret_cast<unsigned*>(&h);
}

// m16n8k16 row.col f16 inputs, f32 accum (C += A*B)
__device__ __forceinline__ void mma16816(float* c, const unsigned* a, const unsigned* b) {
    asm volatile(
        "mma.sync.aligned.m16n8k16.row.col.f32.f16.f16.f32 "
        "{%0,%1,%2,%3}, {%4,%5,%6,%7}, {%8,%9}, {%0,%1,%2,%3};"
        : "+f"(c[0]), "+f"(c[1]), "+f"(c[2]), "+f"(c[3])
        : "r"(a[0]), "r"(a[1]), "r"(a[2]), "r"(a[3]), "r"(b[0]), "r"(b[1]));
}

__device__ __forceinline__ void red_add(int* p) {
    asm volatile("red.global.add.s32 [%0], %1;" :: "l"(p), "r"(1) : "memory");
}

// fragment source values (folded top + raw bottom halves of L matrices)
__device__ __forceinline__ float wzr_at(int k, int n,
                                        const float* LzW, const float* LrW) {
    int g = n >> 5, col = n & 31;
    if (k < 16) return g_A[(g * 16 + k) * 32 + col];
    const float* L = g ? LrW : LzW;
    return L[(k + 16) * 32 + col];          // bottom rows 32..63 of L
}
__device__ __forceinline__ float wh_at(int k, int n, const float* LhW) {
    if (k < 16) return g_A[(2 * 16 + k) * 32 + n];
    return LhW[(k + 16) * 32 + n];
}

// =======================================================================
// k_pre: edge-count + fp16 transpose (coalesced float4 writes) +
//        (block 0) weight fold + softmax + HMMA fragment prebuild
// grid = (N+3)/4 = 12500 blocks of 256
// =======================================================================
__global__ void __launch_bounds__(256)
k_pre(const float* __restrict__ x, const int* __restrict__ ei,
      const float* __restrict__ Wz, const float* __restrict__ bz,
      const float* __restrict__ Wr, const float* __restrict__ br,
      const float* __restrict__ Wh, const float* __restrict__ bh,
      const float* __restrict__ LzW, const float* __restrict__ Lzb,
      const float* __restrict__ LrW, const float* __restrict__ Lrb,
      const float* __restrict__ LhW, const float* __restrict__ Lhb,
      const float* __restrict__ att, int N, int E) {
    __shared__ float sx[4 * FT];
    int tid = threadIdx.x;

    // --- edge-count (fire-and-forget) ---
    int gt = blockIdx.x * 256 + tid;
    if (gt < E) red_add(&g_cnt[__ldg(&ei[E + gt])]);

    // --- transpose: 4 nodes/block, [F][T] f32 -> [T][F] f16, float4 writes ---
    size_t base = (size_t)blockIdx.x * 4 * FT;
    size_t lim  = (size_t)N * FT;
    const float4* x4 = (const float4*)(x + base);
    int nvalid = (int)min((size_t)(4 * FT), lim - base);
    #pragma unroll
    for (int i = tid; i < FT; i += 256) {       // 192 float4s
        if (i * 4 < nvalid) ((float4*)sx)[i] = x4[i];
    }
    __syncthreads();
    if (tid < 96) {                              // 4 nodes x 24 float4 outputs
        int nn  = tid / 24;
        int rem = tid % 24;                      // float4 index within node
        int t = rem >> 1, q = rem & 1;           // q: f-half (0..7 or 8..15)
        int node = blockIdx.x * 4 + nn;
        if (node < N) {
            const float* s = sx + nn * FT + t;   // s[f*TT] pattern
            F4H2 st;
            #pragma unroll
            for (int h = 0; h < 4; h++) {
                int f = q * 8 + 2 * h;
                st.h2[h] = __floats2half2_rn(s[f * TT], s[(f + 1) * TT]);
            }
            ((float4*)(g_xh + (size_t)node * FT))[rem] = st.f4;
        }
    }

    // --- block 0: full fold + softmax + fragment build ---
    if (blockIdx.x == 0) {
        const float* W[3]  = {Wz, Wr, Wh};
        const float* L[3]  = {LzW, LrW, LhW};
        const float* bb[3] = {bz, br, bh};
        const float* Lb[3] = {Lzb, Lrb, Lhb};
        #pragma unroll
        for (int rep = 0; rep < 2; rep++) {
            int id = tid + rep * 256;            // 512 (f,j) pairs
            int f = id >> 5, j = id & 31;
            #pragma unroll
            for (int g = 0; g < 3; g++) {
                float s = 0.0f;
                #pragma unroll
                for (int k = 0; k < HID; k++)
                    s = fmaf(__ldg(&W[g][f * HID + k]), __ldg(&L[g][k * HID + j]), s);
                g_A[(g * FIN + f) * HID + j] = s;
            }
        }
        if (tid < 3 * HID) {
            int g = tid >> 5, jj = tid & 31;
            float s = __ldg(&Lb[g][jj]);
            #pragma unroll
            for (int k = 0; k < HID; k++)
                s = fmaf(__ldg(&bb[g][k]), __ldg(&L[g][k * HID + jj]), s);
            g_c[g * HID + jj] = s;
        }
        if (tid >= 96 && tid < 128) {            // softmax (warp 3)
            int l = tid & 31;
            float v = (l < TT) ? __ldg(&att[l]) : -1e30f;
            float m = v;
            #pragma unroll
            for (int o = 16; o; o >>= 1) m = fmaxf(m, __shfl_xor_sync(0xffffffffu, m, o));
            float e = (l < TT) ? __expf(v - m) : 0.0f;
            float s = e;
            #pragma unroll
            for (int o = 16; o; o >>= 1) s += __shfl_xor_sync(0xffffffffu, s, o);
            if (l < TT) g_probs[l] = e * __fdividef(1.0f, s);
        }
        __syncthreads();
        if (tid < 32) {                          // fragment build (warp 0)
            int l = tid;
            int qr = l >> 2, qc = l & 3;
            #pragma unroll
            for (int s = 0; s < 3; s++) {
                int k0 = 16 * s + 2 * qc;
                #pragma unroll
                for (int jj = 0; jj < 4; jj++) {
                    int j0 = 2 * jj;
                    uint4 v;
                    v.x = h2pack(wzr_at(k0,     8 * j0 + qr, LzW, LrW), wzr_at(k0 + 1, 8 * j0 + qr, LzW, LrW));
                    v.y = h2pack(wzr_at(k0 + 8, 8 * j0 + qr, LzW, LrW), wzr_at(k0 + 9, 8 * j0 + qr, LzW, LrW));
                    v.z = h2pack(wzr_at(k0,     8 * (j0 + 1) + qr, LzW, LrW), wzr_at(k0 + 1, 8 * (j0 + 1) + qr, LzW, LrW));
                    v.w = h2pack(wzr_at(k0 + 8, 8 * (j0 + 1) + qr, LzW, LrW), wzr_at(k0 + 9, 8 * (j0 + 1) + qr, LzW, LrW));
                    g_fzr[s * 4 + jj][l] = v;
                }
                #pragma unroll
                for (int jj = 0; jj < 2; jj++) {
                    int j0 = 2 * jj;
                    uint4 v;
                    v.x = h2pack(wh_at(k0,     8 * j0 + qr, LhW), wh_at(k0 + 1, 8 * j0 + qr, LhW));
                    v.y = h2pack(wh_at(k0 + 8, 8 * j0 + qr, LhW), wh_at(k0 + 9, 8 * j0 + qr, LhW));
                    v.z = h2pack(wh_at(k0,     8 * (j0 + 1) + qr, LhW), wh_at(k0 + 1, 8 * (j0 + 1) + qr, LhW));
                    v.w = h2pack(wh_at(k0 + 8, 8 * (j0 + 1) + qr, LhW), wh_at(k0 + 9, 8 * (j0 + 1) + qr, LhW));
                    g_fh[s * 2 + jj][l] = v;
                }
            }
            #pragma unroll
            for (int i = 0; i < 4; i++) {
                int j0 = 2 * i;
                float4 v;
                v.x = g_c[8 * j0 + 2 * qc];       v.y = g_c[8 * j0 + 2 * qc + 1];
                v.z = g_c[8 * (j0 + 1) + 2 * qc]; v.w = g_c[8 * (j0 + 1) + 2 * qc + 1];
                g_fzc[i][l] = v;
            }
            #pragma unroll
            for (int i = 0; i < 2; i++) {
                int j0 = 2 * i;
                float4 v;
                v.x = g_c[64 + 8 * j0 + 2 * qc];       v.y = g_c[64 + 8 * j0 + 2 * qc + 1];
                v.z = g_c[64 + 8 * (j0 + 1) + 2 * qc]; v.w = g_c[64 + 8 * (j0 + 1) + 2 * qc + 1];
                g_fhc[i][l] = v;
            }
        }
    }
}

// ---- parallel 3-phase scan ----
__global__ void k_scan_a(int N) {
    __shared__ int ws[SB / 32];
    int tid = threadIdx.x;
    int i = blockIdx.x * SB + tid;
    int v = (i < N) ? g_cnt[i] : 0;
    #pragma unroll
    for (int o = 16; o; o >>= 1) v += __shfl_xor_sync(0xffffffffu, v, o);
    if ((tid & 31) == 0) ws[tid >> 5] = v;
    __syncthreads();
    if (tid < SB / 32) {
        int w = ws[tid];
        #pragma unroll
        for (int o = 8; o; o >>= 1) w += __shfl_xor_sync(0xffffu, w, o);
        if (tid == 0) g_part[blockIdx.x] = w;
    }
}

__global__ void k_scan_b(int NB, int N, int E) {
    __shared__ int ws[4];
    int tid = threadIdx.x, lane = tid & 31, wid = tid >> 5;
    int orig = (tid < NB) ? g_part[tid] : 0;
    int v = orig;
    #pragma unroll
    for (int o = 1; o < 32; o <<= 1) {
        int t = __shfl_up_sync(0xffffffffu, v, o);
        if (lane >= o) v += t;
    }
    if (lane == 31) ws[wid] = v;
    __syncthreads();
    if (wid == 0 && lane < 4) {
        int w = ws[lane];
        #pragma unroll
        for (int o = 1; o < 4; o <<= 1) {
            int t = __shfl_up_sync(0xfu, w, o);
            if (lane >= o) w += t;
        }
        ws[lane] = w;
    }
    __syncthreads();
    int incl = v + (wid > 0 ? ws[wid - 1] : 0);
    if (tid < NB) g_part[tid] = incl - orig;     // exclusive
    if (tid == 0) g_rowptr[N] = E;
}

__global__ void k_scan_c(int N) {
    __shared__ int ws[SB / 32];
    int tid = threadIdx.x, lane = tid & 31, wid = tid >> 5;
    int i = blockIdx.x * SB + tid;
    int c = (i < N) ? g_cnt[i] : 0;
    int v = c;
    #pragma unroll
    for (int o = 1; o < 32; o <<= 1) {
        int t = __shfl_up_sync(0xffffffffu, v, o);
        if (lane >= o) v += t;
    }
    if (lane == 31) ws[wid] = v;
    __syncthreads();
    if (wid == 0 && lane < SB / 32) {
        int w = ws[lane];
        #pragma unroll
        for (int o = 1; o < SB / 32; o <<= 1) {
            int t = __shfl_up_sync((1u << (SB / 32)) - 1u, w, o);
            if (lane >= o) w += t;
        }
        ws[lane] = w;
    }
    __syncthreads();
    int excl = v - c + (wid > 0 ? ws[wid - 1] : 0) + g_part[blockIdx.x];
    if (i < N) {
        g_rowptr[i] = excl;
        g_cur[i]    = excl;
        g_dis[i]    = rsqrtf((float)(c + 1));    // +1 self-loop
    }
}

// CSR fill: 4 edges per thread with int4 loads; re-zeros g_cnt.
__global__ void k_fill(const int* __restrict__ ei, int E, int N) {
    int i = blockIdx.x * blockDim.x + threadIdx.x;
    if (i < N) g_cnt[i] = 0;
    int base = i * 4;
    if (base >= E) return;
    int s[4], d[4];
    float ws[4];
    int m;
    if ((E & 3) == 0 && base + 4 <= E) {
        m = 4;
        int4 s4 = __ldg((const int4*)ei + i);
        int4 d4 = __ldg((const int4*)(ei + E) + i);
        s[0] = s4.x; s[1] = s4.y; s[2] = s4.z; s[3] = s4.w;
        d[0] = d4.x; d[1] = d4.y; d[2] = d4.z; d[3] = d4.w;
    } else {
        m = min(4, E - base);
        for (int u = 0; u < m; u++) {
            s[u] = __ldg(&ei[base + u]);
            d[u] = __ldg(&ei[E + base + u]);
        }
    }
    #pragma unroll
    for (int u = 0; u < 4; u++)
        if (u < m) ws[u] = g_dis[s[u]] * g_dis[d[u]];
    #pragma unroll
    for (int u = 0; u < 4; u++) {
        if (u < m) {
            int p = atomicAdd(&g_cur[d[u]], 1);
            g_sw[p] = make_int2(s[u], __float_as_int(ws[u]));
        }
    }
}

// Warp-per-node gather on fp16 features (packed f32x2 accumulation, fp16 out).
__global__ void __launch_bounds__(256)
k_gather(int N) {
    __shared__ int2 stage[8][32];
    int gw   = (blockIdx.x * blockDim.x + threadIdx.x) >> 5;
    int wloc = threadIdx.x >> 5;
    int lane = threadIdx.x & 31;
    if (gw >= N) return;
    int n = gw;

    int beg = g_rowptr[n];
    int end = g_rowptr[n + 1];
    float dd = g_dis[n];
    int ln = (lane < 24) ? lane : 0;        // clamped payload lane

    u64 acc2[4];
    {
        float inv = dd * dd;                       // 1/deg (self-loop term)
        u64 ip = pk2(inv, inv);
        F4H2 v; v.f4 = ((const float4*)(g_xh + (size_t)n * FT))[ln];
        #pragma unroll
        for (int q = 0; q < 4; q++) {
            float2 f = __half22float2(v.h2[q]);
            acc2[q] = fma2(ip, pk2(f.x, f.y), pk2(0.0f, 0.0f));
        }
    }

    for (int i = beg; i < end; i += 32) {
        int j = i + lane;
        if (j < end) stage[wloc][lane] = g_sw[j];
        __syncwarp();
        int m = min(32, end - i);
        #pragma unroll 8
        for (int u = 0; u < m; u++) {
            int2 sw = stage[wloc][u];
            float ww = __int_as_float(sw.y);
            u64 wp = pk2(ww, ww);
            F4H2 v; v.f4 = ((const float4*)(g_xh + (size_t)sw.x * FT))[ln];
            #pragma unroll
            for (int q = 0; q < 4; q++) {
                float2 f = __half22float2(v.h2[q]);
                acc2[q] = fma2(wp, pk2(f.x, f.y), acc2[q]);
            }
        }
        __syncwarp();
    }

    if (lane < 24) {
        F4H2 st;
        #pragma unroll
        for (int q = 0; q < 4; q++) {
            float a0, a1;
            up2(acc2[q], a0, a1);
            st.h2[q] = __floats2half2_rn(a0, a1);
        }
        ((float4*)(g_aggh + (size_t)n * FT))[lane] = st.f4;
    }
}

// ---- tensor-core GRU: warp handles 16 nodes via m16n8k16 HMMA ----
__global__ void __launch_bounds__(128)
k_gru(int N) {
    __shared__ float sp[TT];
    __shared__ float bsum[HID];

    int tid = threadIdx.x;
    if (tid < TT) sp[tid] = g_probs[tid];
    if (tid < HID) bsum[tid] = 0.0f;
    __syncthreads();

    int lane = tid & 31;
    int w = blockIdx.x * 4 + (tid >> 5);
    int NW = (N + 15) / 16;
    if (w < NW) {
        int base = w * 16;
        int qr = lane >> 2;
        int qc = lane & 3;

        // ---- load prebuilt fragments (coalesced) ----
        unsigned bzr[3][8][2];
        unsigned bh[3][4][2];
        float bzc[8][2], bhc[4][2];
        #pragma unroll
        for (int i = 0; i < 12; i++) {
            uint4 v = g_fzr[i][lane];
            int s = i >> 2, j0 = (i & 3) * 2;
            bzr[s][j0][0] = v.x; bzr[s][j0][1] = v.y;
            bzr[s][j0 + 1][0] = v.z; bzr[s][j0 + 1][1] = v.w;
        }
        #pragma unroll
        for (int i = 0; i < 6; i++) {
            uint4 v = g_fh[i][lane];
            int s = i >> 1, j0 = (i & 1) * 2;
            bh[s][j0][0] = v.x; bh[s][j0][1] = v.y;
            bh[s][j0 + 1][0] = v.z; bh[s][j0 + 1][1] = v.w;
        }
        #pragma unroll
        for (int i = 0; i < 4; i++) {
            float4 v = g_fzc[i][lane];
            int j0 = 2 * i;
            bzc[j0][0] = v.x; bzc[j0][1] = v.y;
            bzc[j0 + 1][0] = v.z; bzc[j0 + 1][1] = v.w;
        }
        #pragma unroll
        for (int i = 0; i < 2; i++) {
            float4 v = g_fhc[i][lane];
            int j0 = 2 * i;
            bhc[j0][0] = v.x; bhc[j0][1] = v.y;
            bhc[j0 + 1][0] = v.z; bhc[j0 + 1][1] = v.w;
        }

        int n0 = min(base + qr,     N - 1);
        int n1 = min(base + qr + 8, N - 1);
        const unsigned* A0 = (const unsigned*)(g_aggh + (size_t)n0 * FT) + qc;
        const unsigned* A1 = (const unsigned*)(g_aggh + (size_t)n1 * FT) + qc;

        float H[4][4], acc[4][4];
        #pragma unroll
        for (int j = 0; j < 4; j++)
            #pragma unroll
            for (int i = 0; i < 4; i++) { H[j][i] = 0.0f; acc[j][i] = 0.0f; }

        #pragma unroll 1
        for (int t = 0; t < TT; t++) {
            float p = sp[t];
            unsigned af[4];
            af[0] = A0[t * 8];     af[1] = A1[t * 8];
            af[2] = A0[t * 8 + 4]; af[3] = A1[t * 8 + 4];

            unsigned hA1[4] = { h2pack(H[0][0], H[0][1]), h2pack(H[0][2], H[0][3]),
                                h2pack(H[1][0], H[1][1]), h2pack(H[1][2], H[1][3]) };
            unsigned hA2[4] = { h2pack(H[2][0], H[2][1]), h2pack(H[2][2], H[2][3]),
                                h2pack(H[3][0], H[3][1]), h2pack(H[3][2], H[3][3]) };

            // ---- z,r GEMM ----
            float Czr[8][4];
            #pragma unroll
            for (int j = 0; j < 8; j++) {
                Czr[j][0] = bzc[j][0]; Czr[j][1] = bzc[j][1];
                Czr[j][2] = bzc[j][0]; Czr[j][3] = bzc[j][1];
            }
            #pragma unroll
            for (int j = 0; j < 8; j++) {
                mma16816(Czr[j], af,  bzr[0][j]);
                mma16816(Czr[j], hA1, bzr[1][j]);
                mma16816(Czr[j], hA2, bzr[2][j]);
            }
            float Z[4][4], R[4][4];
            #pragma unroll
            for (int j = 0; j < 4; j++)
                #pragma unroll
                for (int i = 0; i < 4; i++) {
                    Z[j][i] = sigf(Czr[j][i]);
                    R[j][i] = sigf(Czr[4 + j][i]) * H[j][i];
                }

            // ---- candidate GEMM ----
            unsigned rA1[4] = { h2pack(R[0][0], R[0][1]), h2pack(R[0][2], R[0][3]),
                                h2pack(R[1][0], R[1][1]), h2pack(R[1][2], R[1][3]) };
            unsigned rA2[4] = { h2pack(R[2][0], R[2][1]), h2pack(R[2][2], R[2][3]),
                                h2pack(R[3][0], R[3][1]), h2pack(R[3][2], R[3][3]) };
            float Ch[4][4];
            #pragma unroll
            for (int j = 0; j < 4; j++) {
                Ch[j][0] = bhc[j][0]; Ch[j][1] = bhc[j][1];
                Ch[j][2] = bhc[j][0]; Ch[j][3] = bhc[j][1];
            }
            #pragma unroll
            for (int j = 0; j < 4; j++) {
                mma16816(Ch[j], af,  bh[0][j]);
                mma16816(Ch[j], rA1, bh[1][j]);
                mma16816(Ch[j], rA2, bh[2][j]);
            }
            // ---- state update ----
            #pragma unroll
            for (int j = 0; j < 4; j++)
                #pragma unroll
                for (int i = 0; i < 4; i++) {
                    float ht = tanhfast(Ch[j][i]);
                    float z = Z[j][i];
                    H[j][i] = z * H[j][i] + (1.0f - z) * ht;
                    acc[j][i] = fmaf(p, H[j][i], acc[j][i]);
                }
        }

        // ---- relu + reduce ----
        bool v0 = (base + qr)     < N;
        bool v1 = (base + qr + 8) < N;
        #pragma unroll
        for (int j = 0; j < 4; j++) {
            float a0 = acc[j][0], a1 = acc[j][1], a2 = acc[j][2], a3 = acc[j][3];
            float s0 = (v0 ? fmaxf(a0, 0.0f) : 0.0f) + (v1 ? fmaxf(a2, 0.0f) : 0.0f);
            float s1 = (v0 ? fmaxf(a1, 0.0f) : 0.0f) + (v1 ? fmaxf(a3, 0.0f) : 0.0f);
            #pragma unroll
            for (int o = 4; o < 32; o <<= 1) {
                s0 += __shfl_xor_sync(0xffffffffu, s0, o);
                s1 += __shfl_xor_sync(0xffffffffu, s1, o);
            }
            if (qr == 0) {
                atomicAdd(&bsum[8 * j + 2 * qc],     s0);
                atomicAdd(&bsum[8 * j + 2 * qc + 1], s1);
            }
        }
    }
    __syncthreads();
    if (tid < HID) atomicAdd(&g_hsum[tid], bsum[tid]);
}

// Final readout; also re-zeros g_hsum for the next replay.
__global__ void k_final(const float* __restrict__ linW, const float* __restrict__ linb,
                        float* out, int N) {
    int j = threadIdx.x;   // 32 threads
    float invN = 1.0f / (float)N;
    float h = g_hsum[j];
    g_hsum[j] = 0.0f;
    float v = h * invN * linW[j];
    #pragma unroll
    for (int o = 16; o; o >>= 1) v += __shfl_xor_sync(0xffffffffu, v, o);
    if (j == 0) {
        float r = v + linb[0];
        out[0] = r > 0.0f ? r : 0.0f;
    }
}

// ---------------- launcher ----------------
extern "C" void kernel_launch(void* const* d_in, const int* in_sizes, int n_in,
                              void* d_out, int out_size) {
    const float* x    = (const float*)d_in[0];
    const int*   ei   = (const int*)  d_in[1];
    const float* att  = (const float*)d_in[2];
    const float* Wz   = (const float*)d_in[3];
    const float* bz   = (const float*)d_in[4];
    const float* Wr   = (const float*)d_in[5];
    const float* br   = (const float*)d_in[6];
    const float* Wh   = (const float*)d_in[7];
    const float* bh   = (const float*)d_in[8];
    const float* LzW  = (const float*)d_in[9];
    const float* Lzb  = (const float*)d_in[10];
    const float* LrW  = (const float*)d_in[11];
    const float* Lrb  = (const float*)d_in[12];
    const float* LhW  = (const float*)d_in[13];
    const float* Lhb  = (const float*)d_in[14];
    const float* linW = (const float*)d_in[15];
    const float* linb = (const float*)d_in[16];

    int N = in_sizes[0] / FT;
    int E = in_sizes[1] / 2;
    int NB = (N + SB - 1) / SB;
    int NW = (N + 15) / 16;             // gru warps (16 nodes each)
    int NQ = (E + 3) / 4;               // quad-edge fill threads

    k_pre<<<(N + 3) / 4, 256>>>(x, ei, Wz, bz, Wr, br, Wh, bh,
                                LzW, Lzb, LrW, Lrb, LhW, Lhb, att, N, E);
    k_scan_a<<<NB, SB>>>(N);
    k_scan_b<<<1, 128>>>(NB, N, E);
    k_scan_c<<<NB, SB>>>(N);
    k_fill<<<(NQ + 255) / 256, 256>>>(ei, E, N);
    k_gather<<<(N * 32 + 255) / 256, 256>>>(N);
    k_gru<<<(NW + 3) / 4, 128>>>(N);
    k_final<<<1, 32>>>(linW, linb, (float*)d_out, N);
}

// round 15
// speedup vs baseline: 1.5888x; 1.2252x over previous
#include <cuda_runtime.h>
#include <cuda_fp16.h>
#include <math.h>

#define NMAX 50000
#define EMAX 1600000
#define FIN 16
#define TT 12
#define HID 32
#define FT (FIN*TT)   // 192 values per node
#define SB 512        // scan block size

// ---------------- scratch (static device globals; no allocation) ----------------
__device__ int    g_cnt[NMAX];                    // in-degree counts; zeroed by k_fill each run
__device__ int    g_rowptr[NMAX + 1];             // CSR row pointers
__device__ int    g_cur[NMAX];                    // fill cursors
__device__ int2   g_sw[EMAX];                     // CSR payload: {src, bits(norm weight)}
__device__ int    g_part[256];                    // scan partials
__device__ float  g_dis[NMAX];                    // rsqrt(degree incl. self-loop)
__device__ __half g_xh[(size_t)NMAX * FT];        // fp16 features, t-major [N][T][F]
__device__ __half g_aggh[(size_t)NMAX * FT];      // aggregated features fp16, t-major
__device__ float  g_A[3 * FIN * HID];             // folded W_g @ L_g_top
__device__ float  g_c[3 * HID];                   // folded biases
__device__ float  g_probs[TT];                    // softmax(att)
__device__ float  g_hsum[HID];                    // sum over nodes of relu(Hacc); zeroed by k_final

// ---------------- helpers ----------------
__device__ __forceinline__ float sigf(float x) {
    return __fdividef(1.0f, 1.0f + __expf(-x));
}
__device__ __forceinline__ float tanhfast(float x) {
    return fmaf(2.0f, __fdividef(1.0f, 1.0f + __expf(-2.0f * x)), -1.0f);
}
union F4H2 { float4 f4; __half2 h2[4]; };

__device__ __forceinline__ unsigned h2pack(float lo, float hi) {
    __half2 h = __floats2half2_rn(lo, hi);
    return *reinterpret_cast<unsigned*>(&h);
}

// m16n8k16 row.col f16 inputs, f32 accum (C += A*B)
__device__ __forceinline__ void mma16816(float* c, const unsigned* a, const unsigned* b) {
    asm volatile(
        "mma.sync.aligned.m16n8k16.row.col.f32.f16.f16.f32 "
        "{%0,%1,%2,%3}, {%4,%5,%6,%7}, {%8,%9}, {%0,%1,%2,%3};"
        : "+f"(c[0]), "+f"(c[1]), "+f"(c[2]), "+f"(c[3])
        : "r"(a[0]), "r"(a[1]), "r"(a[2]), "r"(a[3]), "r"(b[0]), "r"(b[1]));
}

__device__ __forceinline__ void red_add(int* p) {
    asm volatile("red.global.add.s32 [%0], %1;" :: "l"(p), "r"(1) : "memory");
}

// =======================================================================
// k_pre: edge-count + fp16 transpose + (blocks 0-2) weight fold + softmax
// grid = (N+3)/4 = 12500 blocks of 256   [exact R11 form — measured fast]
// =======================================================================
__global__ void __launch_bounds__(256)
k_pre(const float* __restrict__ x, const int* __restrict__ ei,
      const float* __restrict__ Wz, const float* __restrict__ bz,
      const float* __restrict__ Wr, const float* __restrict__ br,
      const float* __restrict__ Wh, const float* __restrict__ bh,
      const float* __restrict__ LzW, const float* __restrict__ Lzb,
      const float* __restrict__ LrW, const float* __restrict__ Lrb,
      const float* __restrict__ LhW, const float* __restrict__ Lhb,
      const float* __restrict__ att, int N, int E) {
    __shared__ float sx[4 * FT];
    int tid = threadIdx.x;

    // --- edge-count (fire-and-forget) ---
    int gt = blockIdx.x * 256 + tid;
    if (gt < E) red_add(&g_cnt[__ldg(&ei[E + gt])]);

    // --- conversion: 4 nodes per block, [N][F][T] f32 -> [N][T][F] f16 ---
    size_t base = (size_t)blockIdx.x * 4 * FT;
    size_t lim  = (size_t)N * FT;
    #pragma unroll
    for (int i = tid; i < 4 * FT; i += 256) {
        size_t g = base + i;
        if (g < lim) sx[i] = x[g];
    }
    __syncthreads();
    {
        int nn = tid >> 6, u = tid & 63;
        int node = blockIdx.x * 4 + nn;
        if (node < N) {
            const float* s = sx + nn * FT;
            __half* d = g_xh + (size_t)node * FT;
            #pragma unroll
            for (int r = 0; r < 3; r++) {
                int o = (r << 6) + u;               // output index (t-major)
                int t = o >> 4, f = o & 15;
                d[o] = __float2half(s[f * TT + t]);
            }
        }
    }

    // --- weight fold: block g in {0,1,2} handles gate g ---
    if (blockIdx.x < 3) {
        int g = blockIdx.x;
        const float* W  = (g == 0) ? Wz : (g == 1) ? Wr : Wh;
        const float* L  = (g == 0) ? LzW : (g == 1) ? LrW : LhW;
        const float* bb = (g == 0) ? bz : (g == 1) ? br : bh;
        const float* Lb = (g == 0) ? Lzb : (g == 1) ? Lrb : Lhb;
        #pragma unroll
        for (int rep = 0; rep < 2; rep++) {
            int id = tid + rep * 256;           // 512 (f,j) pairs
            int f = id >> 5, j = id & 31;
            float s = 0.0f;
            #pragma unroll
            for (int k = 0; k < HID; k++)
                s = fmaf(__ldg(&W[f * HID + k]), __ldg(&L[k * HID + j]), s);
            g_A[(g * FIN + f) * HID + j] = s;
        }
        if (tid < HID) {
            float s = __ldg(&Lb[tid]);
            #pragma unroll
            for (int k = 0; k < HID; k++)
                s = fmaf(__ldg(&bb[k]), __ldg(&L[k * HID + tid]), s);
            g_c[g * HID + tid] = s;
        }
        if (g == 0 && tid >= 32 && tid < 64) {  // softmax on warp 1
            int l = tid & 31;
            float v = (l < TT) ? __ldg(&att[l]) : -1e30f;
            float m = v;
            #pragma unroll
            for (int o = 16; o; o >>= 1) m = fmaxf(m, __shfl_xor_sync(0xffffffffu, m, o));
            float e = (l < TT) ? __expf(v - m) : 0.0f;
            float s = e;
            #pragma unroll
            for (int o = 16; o; o >>= 1) s += __shfl_xor_sync(0xffffffffu, s, o);
            if (l < TT) g_probs[l] = e * __fdividef(1.0f, s);
        }
    }
}

// ---- parallel 3-phase scan ----
__global__ void k_scan_a(int N) {
    __shared__ int ws[SB / 32];
    int tid = threadIdx.x;
    int i = blockIdx.x * SB + tid;
    int v = (i < N) ? g_cnt[i] : 0;
    #pragma unroll
    for (int o = 16; o; o >>= 1) v += __shfl_xor_sync(0xffffffffu, v, o);
    if ((tid & 31) == 0) ws[tid >> 5] = v;
    __syncthreads();
    if (tid < SB / 32) {
        int w = ws[tid];
        #pragma unroll
        for (int o = 8; o; o >>= 1) w += __shfl_xor_sync(0xffffu, w, o);
        if (tid == 0) g_part[blockIdx.x] = w;
    }
}

__global__ void k_scan_b(int NB, int N, int E) {
    __shared__ int ws[4];
    int tid = threadIdx.x, lane = tid & 31, wid = tid >> 5;
    int orig = (tid < NB) ? g_part[tid] : 0;
    int v = orig;
    #pragma unroll
    for (int o = 1; o < 32; o <<= 1) {
        int t = __shfl_up_sync(0xffffffffu, v, o);
        if (lane >= o) v += t;
    }
    if (lane == 31) ws[wid] = v;
    __syncthreads();
    if (wid == 0 && lane < 4) {
        int w = ws[lane];
        #pragma unroll
        for (int o = 1; o < 4; o <<= 1) {
            int t = __shfl_up_sync(0xfu, w, o);
            if (lane >= o) w += t;
        }
        ws[lane] = w;
    }
    __syncthreads();
    int incl = v + (wid > 0 ? ws[wid - 1] : 0);
    if (tid < NB) g_part[tid] = incl - orig;     // exclusive
    if (tid == 0) g_rowptr[N] = E;
}

__global__ void k_scan_c(int N) {
    __shared__ int ws[SB / 32];
    int tid = threadIdx.x, lane = tid & 31, wid = tid >> 5;
    int i = blockIdx.x * SB + tid;
    int c = (i < N) ? g_cnt[i] : 0;
    int v = c;
    #pragma unroll
    for (int o = 1; o < 32; o <<= 1) {
        int t = __shfl_up_sync(0xffffffffu, v, o);
        if (lane >= o) v += t;
    }
    if (lane == 31) ws[wid] = v;
    __syncthreads();
    if (wid == 0 && lane < SB / 32) {
        int w = ws[lane];
        #pragma unroll
        for (int o = 1; o < SB / 32; o <<= 1) {
            int t = __shfl_up_sync((1u << (SB / 32)) - 1u, w, o);
            if (lane >= o) w += t;
        }
        ws[lane] = w;
    }
    __syncthreads();
    int excl = v - c + (wid > 0 ? ws[wid - 1] : 0) + g_part[blockIdx.x];
    if (i < N) {
        g_rowptr[i] = excl;
        g_cur[i]    = excl;
        g_dis[i]    = rsqrtf((float)(c + 1));    // +1 self-loop
    }
}

// CSR fill: 4 edges per thread (batched scalar loads); re-zeros g_cnt.
__global__ void k_fill(const int* __restrict__ ei, int E, int N) {
    int i = blockIdx.x * blockDim.x + threadIdx.x;
    if (i < N) g_cnt[i] = 0;
    int base = i * 4;
    if (base >= E) return;
    int m = min(4, E - base);
    int s[4], d[4];
    float ws[4];
    #pragma unroll
    for (int u = 0; u < 4; u++) {
        if (u < m) {
            s[u] = __ldg(&ei[base + u]);
            d[u] = __ldg(&ei[E + base + u]);
        }
    }
    #pragma unroll
    for (int u = 0; u < 4; u++)
        if (u < m) ws[u] = g_dis[s[u]] * g_dis[d[u]];
    #pragma unroll
    for (int u = 0; u < 4; u++) {
        if (u < m) {
            int p = atomicAdd(&g_cur[d[u]], 1);
            g_sw[p] = make_int2(s[u], __float_as_int(ws[u]));
        }
    }
}

// Warp-per-node gather on fp16 features — packed HFMA2 accumulation.
// Per edge: 1 LDS (stage) + 1 cvt (w->half2) + 1 LDG.128 + 4 HFMA2.
__global__ void __launch_bounds__(256)
k_gather(int N) {
    __shared__ int2 stage[8][32];
    int gw   = (blockIdx.x * blockDim.x + threadIdx.x) >> 5;
    int wloc = threadIdx.x >> 5;
    int lane = threadIdx.x & 31;
    if (gw >= N) return;
    int n = gw;

    int beg = g_rowptr[n];
    int end = g_rowptr[n + 1];
    float dd = g_dis[n];
    int ln = (lane < 24) ? lane : 0;        // clamped payload lane

    __half2 acc[4];
    {
        float inv = dd * dd;                       // 1/deg (self-loop term)
        __half2 ih = __float2half2_rn(inv);
        F4H2 v; v.f4 = ((const float4*)(g_xh + (size_t)n * FT))[ln];
        #pragma unroll
        for (int q = 0; q < 4; q++) acc[q] = __hmul2(ih, v.h2[q]);
    }

    for (int i = beg; i < end; i += 32) {
        int j = i + lane;
        if (j < end) stage[wloc][lane] = g_sw[j];
        __syncwarp();
        int m = min(32, end - i);
        #pragma unroll 8
        for (int u = 0; u < m; u++) {
            int2 sw = stage[wloc][u];
            __half2 wh = __float2half2_rn(__int_as_float(sw.y));
            F4H2 v; v.f4 = ((const float4*)(g_xh + (size_t)sw.x * FT))[ln];
            #pragma unroll
            for (int q = 0; q < 4; q++)
                acc[q] = __hfma2(wh, v.h2[q], acc[q]);
        }
        __syncwarp();
    }

    if (lane < 24) {
        F4H2 st;
        #pragma unroll
        for (int q = 0; q < 4; q++) st.h2[q] = acc[q];
        ((float4*)(g_aggh + (size_t)n * FT))[lane] = st.f4;
    }
}

// ---- tensor-core GRU: warp handles 16 nodes via m16n8k16 HMMA ----
__device__ __forceinline__ float wzr_at(int k, int n,
                                        const float* LzW, const float* LrW) {
    int g = n >> 5, col = n & 31;
    if (k < 16) return g_A[(g * 16 + k) * 32 + col];
    const float* L = g ? LrW : LzW;
    return L[(k + 16) * 32 + col];          // bottom rows 32..63 of L
}
__device__ __forceinline__ float wh_at(int k, int n, const float* LhW) {
    if (k < 16) return g_A[(2 * 16 + k) * 32 + n];
    return LhW[(k + 16) * 32 + n];
}

__global__ void __launch_bounds__(128)
k_gru(const float* __restrict__ LzW, const float* __restrict__ LrW,
      const float* __restrict__ LhW, int N) {
    __shared__ float sp[TT];
    __shared__ float bsum[HID];

    int tid = threadIdx.x;
    if (tid < TT) sp[tid] = g_probs[tid];
    if (tid < HID) bsum[tid] = 0.0f;
    __syncthreads();

    int lane = tid & 31;
    int w = blockIdx.x * 4 + (tid >> 5);
    int NW = (N + 15) / 16;
    if (w < NW) {
        int base = w * 16;
        int qr = lane >> 2;         // row 0..7 (also n within 8-col tile for B)
        int qc = lane & 3;          // col-pair 0..3

        // ---- weight B-fragments (once) ----
        unsigned bzr[3][8][2];      // k-tile s, n-tile j
        unsigned bh[3][4][2];
        #pragma unroll
        for (int s = 0; s < 3; s++) {
            int k0 = 16 * s + 2 * qc;
            #pragma unroll
            for (int j = 0; j < 8; j++) {
                int n = 8 * j + qr;
                bzr[s][j][0] = h2pack(wzr_at(k0,     n, LzW, LrW), wzr_at(k0 + 1, n, LzW, LrW));
                bzr[s][j][1] = h2pack(wzr_at(k0 + 8, n, LzW, LrW), wzr_at(k0 + 9, n, LzW, LrW));
            }
            #pragma unroll
            for (int j = 0; j < 4; j++) {
                int n = 8 * j + qr;
                bh[s][j][0] = h2pack(wh_at(k0,     n, LhW), wh_at(k0 + 1, n, LhW));
                bh[s][j][1] = h2pack(wh_at(k0 + 8, n, LhW), wh_at(k0 + 9, n, LhW));
            }
        }
        // ---- bias fragments ----
        float bzc[8][2], bhc[4][2];
        #pragma unroll
        for (int j = 0; j < 8; j++) {
            int n = 8 * j + 2 * qc;
            bzc[j][0] = g_c[n]; bzc[j][1] = g_c[n + 1];
        }
        #pragma unroll
        for (int j = 0; j < 4; j++) {
            int n = 8 * j + 2 * qc;
            bhc[j][0] = g_c[64 + n]; bhc[j][1] = g_c[64 + n + 1];
        }

        int n0 = min(base + qr,     N - 1);
        int n1 = min(base + qr + 8, N - 1);
        const unsigned* A0 = (const unsigned*)(g_aggh + (size_t)n0 * FT) + qc;
        const unsigned* A1 = (const unsigned*)(g_aggh + (size_t)n1 * FT) + qc;

        float H[4][4], acc[4][4];
        #pragma unroll
        for (int j = 0; j < 4; j++)
            #pragma unroll
            for (int i = 0; i < 4; i++) { H[j][i] = 0.0f; acc[j][i] = 0.0f; }

        #pragma unroll 1
        for (int t = 0; t < TT; t++) {
            float p = sp[t];
            unsigned af[4];
            af[0] = A0[t * 8];     af[1] = A1[t * 8];
            af[2] = A0[t * 8 + 4]; af[3] = A1[t * 8 + 4];

            unsigned hA1[4] = { h2pack(H[0][0], H[0][1]), h2pack(H[0][2], H[0][3]),
                                h2pack(H[1][0], H[1][1]), h2pack(H[1][2], H[1][3]) };
            unsigned hA2[4] = { h2pack(H[2][0], H[2][1]), h2pack(H[2][2], H[2][3]),
                                h2pack(H[3][0], H[3][1]), h2pack(H[3][2], H[3][3]) };

            // ---- z,r GEMM ----
            float Czr[8][4];
            #pragma unroll
            for (int j = 0; j < 8; j++) {
                Czr[j][0] = bzc[j][0]; Czr[j][1] = bzc[j][1];
                Czr[j][2] = bzc[j][0]; Czr[j][3] = bzc[j][1];
            }
            #pragma unroll
            for (int j = 0; j < 8; j++) {
                mma16816(Czr[j], af,  bzr[0][j]);
                mma16816(Czr[j], hA1, bzr[1][j]);
                mma16816(Czr[j], hA2, bzr[2][j]);
            }
            float Z[4][4], R[4][4];
            #pragma unroll
            for (int j = 0; j < 4; j++)
                #pragma unroll
                for (int i = 0; i < 4; i++) {
                    Z[j][i] = sigf(Czr[j][i]);
                    R[j][i] = sigf(Czr[4 + j][i]) * H[j][i];
                }

            // ---- candidate GEMM ----
            unsigned rA1[4] = { h2pack(R[0][0], R[0][1]), h2pack(R[0][2], R[0][3]),
                                h2pack(R[1][0], R[1][1]), h2pack(R[1][2], R[1][3]) };
            unsigned rA2[4] = { h2pack(R[2][0], R[2][1]), h2pack(R[2][2], R[2][3]),
                                h2pack(R[3][0], R[3][1]), h2pack(R[3][2], R[3][3]) };
            float Ch[4][4];
            #pragma unroll
            for (int j = 0; j < 4; j++) {
                Ch[j][0] = bhc[j][0]; Ch[j][1] = bhc[j][1];
                Ch[j][2] = bhc[j][0]; Ch[j][3] = bhc[j][1];
            }
            #pragma unroll
            for (int j = 0; j < 4; j++) {
                mma16816(Ch[j], af,  bh[0][j]);
                mma16816(Ch[j], rA1, bh[1][j]);
                mma16816(Ch[j], rA2, bh[2][j]);
            }
            // ---- state update ----
            #pragma unroll
            for (int j = 0; j < 4; j++)
                #pragma unroll
                for (int i = 0; i < 4; i++) {
                    float ht = tanhfast(Ch[j][i]);
                    float z = Z[j][i];
                    H[j][i] = z * H[j][i] + (1.0f - z) * ht;
                    acc[j][i] = fmaf(p, H[j][i], acc[j][i]);
                }
        }

        // ---- relu + reduce ----
        bool v0 = (base + qr)     < N;
        bool v1 = (base + qr + 8) < N;
        #pragma unroll
        for (int j = 0; j < 4; j++) {
            float a0 = acc[j][0], a1 = acc[j][1], a2 = acc[j][2], a3 = acc[j][3];
            float s0 = (v0 ? fmaxf(a0, 0.0f) : 0.0f) + (v1 ? fmaxf(a2, 0.0f) : 0.0f);
            float s1 = (v0 ? fmaxf(a1, 0.0f) : 0.0f) + (v1 ? fmaxf(a3, 0.0f) : 0.0f);
            #pragma unroll
            for (int o = 4; o < 32; o <<= 1) {
                s0 += __shfl_xor_sync(0xffffffffu, s0, o);
                s1 += __shfl_xor_sync(0xffffffffu, s1, o);
            }
            if (qr == 0) {
                atomicAdd(&bsum[8 * j + 2 * qc],     s0);
                atomicAdd(&bsum[8 * j + 2 * qc + 1], s1);
            }
        }
    }
    __syncthreads();
    if (tid < HID) atomicAdd(&g_hsum[tid], bsum[tid]);
}

// Final readout; also re-zeros g_hsum for the next replay.
__global__ void k_final(const float* __restrict__ linW, const float* __restrict__ linb,
                        float* out, int N) {
    int j = threadIdx.x;   // 32 threads
    float invN = 1.0f / (float)N;
    float h = g_hsum[j];
    g_hsum[j] = 0.0f;
    float v = h * invN * linW[j];
    #pragma unroll
    for (int o = 16; o; o >>= 1) v += __shfl_xor_sync(0xffffffffu, v, o);
    if (j == 0) {
        float r = v + linb[0];
        out[0] = r > 0.0f ? r : 0.0f;
    }
}

// ---------------- launcher ----------------
extern "C" void kernel_launch(void* const* d_in, const int* in_sizes, int n_in,
                              void* d_out, int out_size) {
    const float* x    = (const float*)d_in[0];
    const int*   ei   = (const int*)  d_in[1];
    const float* att  = (const float*)d_in[2];
    const float* Wz   = (const float*)d_in[3];
    const float* bz   = (const float*)d_in[4];
    const float* Wr   = (const float*)d_in[5];
    const float* br   = (const float*)d_in[6];
    const float* Wh   = (const float*)d_in[7];
    const float* bh   = (const float*)d_in[8];
    const float* LzW  = (const float*)d_in[9];
    const float* Lzb  = (const float*)d_in[10];
    const float* LrW  = (const float*)d_in[11];
    const float* Lrb  = (const float*)d_in[12];
    const float* LhW  = (const float*)d_in[13];
    const float* Lhb  = (const float*)d_in[14];
    const float* linW = (const float*)d_in[15];
    const float* linb = (const float*)d_in[16];

    int N = in_sizes[0] / FT;
    int E = in_sizes[1] / 2;
    int NB = (N + SB - 1) / SB;
    int NW = (N + 15) / 16;             // gru warps (16 nodes each)
    int NF = (E + 3) / 4;               // fill threads (4 edges each)

    k_pre<<<(N + 3) / 4, 256>>>(x, ei, Wz, bz, Wr, br, Wh, bh,
                                LzW, Lzb, LrW, Lrb, LhW, Lhb, att, N, E);
    k_scan_a<<<NB, SB>>>(N);
    k_scan_b<<<1, 128>>>(NB, N, E);
    k_scan_c<<<NB, SB>>>(N);
    k_fill<<<(NF + 255) / 256, 256>>>(ei, E, N);
    k_gather<<<(N * 32 + 255) / 256, 256>>>(N);
    k_gru<<<(NW + 3) / 4, 128>>>(LzW, LrW, LhW, N);
    k_final<<<1, 32>>>(linW, linb, (float*)d_out, N);
}

// round 16
// speedup vs baseline: 1.7918x; 1.1278x over previous
#include <cuda_runtime.h>
#include <cuda_fp16.h>
#include <math.h>

#define NMAX 50000
#define EMAX 1600000
#define FIN 16
#define TT 12
#define HID 32
#define FT (FIN*TT)   // 192 values per node
#define SB 512        // scan block size

// ---------------- scratch (static device globals; no allocation) ----------------
__device__ int    g_cnt[NMAX];                    // in-degree counts; zeroed by k_fill each run
__device__ int    g_rowptr[NMAX + 1];             // CSR row pointers
__device__ int    g_cur[NMAX];                    // fill cursors
__device__ int2   g_sw[EMAX];                     // CSR payload: {src, bits(norm weight)}
__device__ int    g_part[256];                    // scan partials (raw per-block sums)
__device__ float  g_dis[NMAX];                    // rsqrt(degree incl. self-loop)
__device__ __half g_xh[(size_t)NMAX * FT];        // fp16 features, t-major [N][T][F]
__device__ __half g_aggh[(size_t)NMAX * FT];      // aggregated features fp16, t-major
__device__ float  g_A[3 * FIN * HID];             // folded W_g @ L_g_top
__device__ float  g_c[3 * HID];                   // folded biases
__device__ float  g_probs[TT];                    // softmax(att)
__device__ float  g_hsum[HID];                    // sum over nodes of relu(Hacc); zeroed by k_final

// ---------------- helpers ----------------
__device__ __forceinline__ float tanhapx(float x) {
    float y; asm("tanh.approx.f32 %0, %1;" : "=f"(y) : "f"(x)); return y;
}
__device__ __forceinline__ float sigapx(float x) {
    return fmaf(0.5f, tanhapx(0.5f * x), 0.5f);
}
union F4H2 { float4 f4; __half2 h2[4]; };

__device__ __forceinline__ unsigned h2pack(float lo, float hi) {
    __half2 h = __floats2half2_rn(lo, hi);
    return *reinterpret_cast<unsigned*>(&h);
}

// m16n8k16 row.col f16 inputs, f32 accum (C += A*B)
__device__ __forceinline__ void mma16816(float* c, const unsigned* a, const unsigned* b) {
    asm volatile(
        "mma.sync.aligned.m16n8k16.row.col.f32.f16.f16.f32 "
        "{%0,%1,%2,%3}, {%4,%5,%6,%7}, {%8,%9}, {%0,%1,%2,%3};"
        : "+f"(c[0]), "+f"(c[1]), "+f"(c[2]), "+f"(c[3])
        : "r"(a[0]), "r"(a[1]), "r"(a[2]), "r"(a[3]), "r"(b[0]), "r"(b[1]));
}

__device__ __forceinline__ void red_add(int* p) {
    asm volatile("red.global.add.s32 [%0], %1;" :: "l"(p), "r"(1) : "memory");
}

// =======================================================================
// k_pre: edge-count + fp16 transpose + (blocks 0-2) weight fold + softmax
// grid = (N+3)/4 = 12500 blocks of 256   [exact R11/R15 form — measured fast]
// =======================================================================
__global__ void __launch_bounds__(256)
k_pre(const float* __restrict__ x, const int* __restrict__ ei,
      const float* __restrict__ Wz, const float* __restrict__ bz,
      const float* __restrict__ Wr, const float* __restrict__ br,
      const float* __restrict__ Wh, const float* __restrict__ bh,
      const float* __restrict__ LzW, const float* __restrict__ Lzb,
      const float* __restrict__ LrW, const float* __restrict__ Lrb,
      const float* __restrict__ LhW, const float* __restrict__ Lhb,
      const float* __restrict__ att, int N, int E) {
    __shared__ float sx[4 * FT];
    int tid = threadIdx.x;

    // --- edge-count (fire-and-forget) ---
    int gt = blockIdx.x * 256 + tid;
    if (gt < E) red_add(&g_cnt[__ldg(&ei[E + gt])]);

    // --- conversion: 4 nodes per block, [N][F][T] f32 -> [N][T][F] f16 ---
    size_t base = (size_t)blockIdx.x * 4 * FT;
    size_t lim  = (size_t)N * FT;
    #pragma unroll
    for (int i = tid; i < 4 * FT; i += 256) {
        size_t g = base + i;
        if (g < lim) sx[i] = x[g];
    }
    __syncthreads();
    {
        int nn = tid >> 6, u = tid & 63;
        int node = blockIdx.x * 4 + nn;
        if (node < N) {
            const float* s = sx + nn * FT;
            __half* d = g_xh + (size_t)node * FT;
            #pragma unroll
            for (int r = 0; r < 3; r++) {
                int o = (r << 6) + u;               // output index (t-major)
                int t = o >> 4, f = o & 15;
                d[o] = __float2half(s[f * TT + t]);
            }
        }
    }

    // --- weight fold: block g in {0,1,2} handles gate g ---
    if (blockIdx.x < 3) {
        int g = blockIdx.x;
        const float* W  = (g == 0) ? Wz : (g == 1) ? Wr : Wh;
        const float* L  = (g == 0) ? LzW : (g == 1) ? LrW : LhW;
        const float* bb = (g == 0) ? bz : (g == 1) ? br : bh;
        const float* Lb = (g == 0) ? Lzb : (g == 1) ? Lrb : Lhb;
        #pragma unroll
        for (int rep = 0; rep < 2; rep++) {
            int id = tid + rep * 256;           // 512 (f,j) pairs
            int f = id >> 5, j = id & 31;
            float s = 0.0f;
            #pragma unroll
            for (int k = 0; k < HID; k++)
                s = fmaf(__ldg(&W[f * HID + k]), __ldg(&L[k * HID + j]), s);
            g_A[(g * FIN + f) * HID + j] = s;
        }
        if (tid < HID) {
            float s = __ldg(&Lb[tid]);
            #pragma unroll
            for (int k = 0; k < HID; k++)
                s = fmaf(__ldg(&bb[k]), __ldg(&L[k * HID + tid]), s);
            g_c[g * HID + tid] = s;
        }
        if (g == 0 && tid >= 32 && tid < 64) {  // softmax on warp 1
            int l = tid & 31;
            float v = (l < TT) ? __ldg(&att[l]) : -1e30f;
            float m = v;
            #pragma unroll
            for (int o = 16; o; o >>= 1) m = fmaxf(m, __shfl_xor_sync(0xffffffffu, m, o));
            float e = (l < TT) ? __expf(v - m) : 0.0f;
            float s = e;
            #pragma unroll
            for (int o = 16; o; o >>= 1) s += __shfl_xor_sync(0xffffffffu, s, o);
            if (l < TT) g_probs[l] = e * __fdividef(1.0f, s);
        }
    }
}

// ---- scan phase A: per-block reduction of counts (raw sums into g_part) ----
__global__ void k_scan_a(int N) {
    __shared__ int ws[SB / 32];
    int tid = threadIdx.x;
    int i = blockIdx.x * SB + tid;
    int v = (i < N) ? g_cnt[i] : 0;
    #pragma unroll
    for (int o = 16; o; o >>= 1) v += __shfl_xor_sync(0xffffffffu, v, o);
    if ((tid & 31) == 0) ws[tid >> 5] = v;
    __syncthreads();
    if (tid < SB / 32) {
        int w = ws[tid];
        #pragma unroll
        for (int o = 8; o; o >>= 1) w += __shfl_xor_sync(0xffffu, w, o);
        if (tid == 0) g_part[blockIdx.x] = w;
    }
}

// ---- scan phase C: each block reduces its own base from raw partials,
//      then block-local exclusive scan; writes rowptr/cur/dis. (phase B gone)
__global__ void k_scan_c(int N, int E, int NB) {
    __shared__ int rs[SB / 32];
    __shared__ int ws[SB / 32];
    __shared__ int sbase;
    int tid = threadIdx.x, lane = tid & 31, wid = tid >> 5;
    int b = blockIdx.x;

    // base = sum of g_part[0..b-1]  (NB <= 98 < 512, one value per thread)
    int p = (tid < b) ? g_part[tid] : 0;
    #pragma unroll
    for (int o = 16; o; o >>= 1) p += __shfl_xor_sync(0xffffffffu, p, o);
    if (lane == 0) rs[wid] = p;
    __syncthreads();
    if (tid == 0) {
        int s = 0;
        #pragma unroll
        for (int k = 0; k < SB / 32; k++) s += rs[k];
        sbase = s;
    }

    // block-local inclusive scan of counts
    int i = b * SB + tid;
    int c = (i < N) ? g_cnt[i] : 0;
    int v = c;
    #pragma unroll
    for (int o = 1; o < 32; o <<= 1) {
        int t = __shfl_up_sync(0xffffffffu, v, o);
        if (lane >= o) v += t;
    }
    if (lane == 31) ws[wid] = v;
    __syncthreads();
    if (wid == 0 && lane < SB / 32) {
        int w = ws[lane];
        #pragma unroll
        for (int o = 1; o < SB / 32; o <<= 1) {
            int t = __shfl_up_sync((1u << (SB / 32)) - 1u, w, o);
            if (lane >= o) w += t;
        }
        ws[lane] = w;
    }
    __syncthreads();
    int excl = v - c + (wid > 0 ? ws[wid - 1] : 0) + sbase;
    if (i < N) {
        g_rowptr[i] = excl;
        g_cur[i]    = excl;
        g_dis[i]    = rsqrtf((float)(c + 1));    // +1 self-loop
    }
    if (b == NB - 1 && tid == 0) g_rowptr[N] = E;
}

// CSR fill: 4 edges per thread (batched scalar loads); re-zeros g_cnt.
__global__ void k_fill(const int* __restrict__ ei, int E, int N) {
    int i = blockIdx.x * blockDim.x + threadIdx.x;
    if (i < N) g_cnt[i] = 0;
    int base = i * 4;
    if (base >= E) return;
    int m = min(4, E - base);
    int s[4], d[4];
    float ws[4];
    #pragma unroll
    for (int u = 0; u < 4; u++) {
        if (u < m) {
            s[u] = __ldg(&ei[base + u]);
            d[u] = __ldg(&ei[E + base + u]);
        }
    }
    #pragma unroll
    for (int u = 0; u < 4; u++)
        if (u < m) ws[u] = g_dis[s[u]] * g_dis[d[u]];
    #pragma unroll
    for (int u = 0; u < 4; u++) {
        if (u < m) {
            int p = atomicAdd(&g_cur[d[u]], 1);
            g_sw[p] = make_int2(s[u], __float_as_int(ws[u]));
        }
    }
}

// Warp-per-node gather on fp16 features — packed HFMA2 accumulation.
__global__ void __launch_bounds__(256)
k_gather(int N) {
    __shared__ int2 stage[8][32];
    int gw   = (blockIdx.x * blockDim.x + threadIdx.x) >> 5;
    int wloc = threadIdx.x >> 5;
    int lane = threadIdx.x & 31;
    if (gw >= N) return;
    int n = gw;

    int beg = g_rowptr[n];
    int end = g_rowptr[n + 1];
    float dd = g_dis[n];
    int ln = (lane < 24) ? lane : 0;        // clamped payload lane

    __half2 acc[4];
    {
        float inv = dd * dd;                       // 1/deg (self-loop term)
        __half2 ih = __float2half2_rn(inv);
        F4H2 v; v.f4 = ((const float4*)(g_xh + (size_t)n * FT))[ln];
        #pragma unroll
        for (int q = 0; q < 4; q++) acc[q] = __hmul2(ih, v.h2[q]);
    }

    for (int i = beg; i < end; i += 32) {
        int j = i + lane;
        if (j < end) stage[wloc][lane] = g_sw[j];
        __syncwarp();
        int m = min(32, end - i);
        #pragma unroll 8
        for (int u = 0; u < m; u++) {
            int2 sw = stage[wloc][u];
            __half2 wh = __float2half2_rn(__int_as_float(sw.y));
            F4H2 v; v.f4 = ((const float4*)(g_xh + (size_t)sw.x * FT))[ln];
            #pragma unroll
            for (int q = 0; q < 4; q++)
                acc[q] = __hfma2(wh, v.h2[q], acc[q]);
        }
        __syncwarp();
    }

    if (lane < 24) {
        F4H2 st;
        #pragma unroll
        for (int q = 0; q < 4; q++) st.h2[q] = acc[q];
        ((float4*)(g_aggh + (size_t)n * FT))[lane] = st.f4;
    }
}

// ---- tensor-core GRU: warp handles 16 nodes via m16n8k16 HMMA ----
__device__ __forceinline__ float wzr_at(int k, int n,
                                        const float* LzW, const float* LrW) {
    int g = n >> 5, col = n & 31;
    if (k < 16) return g_A[(g * 16 + k) * 32 + col];
    const float* L = g ? LrW : LzW;
    return L[(k + 16) * 32 + col];          // bottom rows 32..63 of L
}
__device__ __forceinline__ float wh_at(int k, int n, const float* LhW) {
    if (k < 16) return g_A[(2 * 16 + k) * 32 + n];
    return LhW[(k + 16) * 32 + n];
}

__global__ void __launch_bounds__(128)
k_gru(const float* __restrict__ LzW, const float* __restrict__ LrW,
      const float* __restrict__ LhW, int N) {
    __shared__ float sp[TT];
    __shared__ float bsum[HID];

    int tid = threadIdx.x;
    if (tid < TT) sp[tid] = g_probs[tid];
    if (tid < HID) bsum[tid] = 0.0f;
    __syncthreads();

    int lane = tid & 31;
    int w = blockIdx.x * 4 + (tid >> 5);
    int NW = (N + 15) / 16;
    if (w < NW) {
        int base = w * 16;
        int qr = lane >> 2;         // row 0..7 (also n within 8-col tile for B)
        int qc = lane & 3;          // col-pair 0..3

        // ---- weight B-fragments (once) ----
        unsigned bzr[3][8][2];      // k-tile s, n-tile j
        unsigned bh[3][4][2];
        #pragma unroll
        for (int s = 0; s < 3; s++) {
            int k0 = 16 * s + 2 * qc;
            #pragma unroll
            for (int j = 0; j < 8; j++) {
                int n = 8 * j + qr;
                bzr[s][j][0] = h2pack(wzr_at(k0,     n, LzW, LrW), wzr_at(k0 + 1, n, LzW, LrW));
                bzr[s][j][1] = h2pack(wzr_at(k0 + 8, n, LzW, LrW), wzr_at(k0 + 9, n, LzW, LrW));
            }
            #pragma unroll
            for (int j = 0; j < 4; j++) {
                int n = 8 * j + qr;
                bh[s][j][0] = h2pack(wh_at(k0,     n, LhW), wh_at(k0 + 1, n, LhW));
                bh[s][j][1] = h2pack(wh_at(k0 + 8, n, LhW), wh_at(k0 + 9, n, LhW));
            }
        }
        // ---- bias fragments ----
        float bzc[8][2], bhc[4][2];
        #pragma unroll
        for (int j = 0; j < 8; j++) {
            int n = 8 * j + 2 * qc;
            bzc[j][0] = g_c[n]; bzc[j][1] = g_c[n + 1];
        }
        #pragma unroll
        for (int j = 0; j < 4; j++) {
            int n = 8 * j + 2 * qc;
            bhc[j][0] = g_c[64 + n]; bhc[j][1] = g_c[64 + n + 1];
        }

        int n0 = min(base + qr,     N - 1);
        int n1 = min(base + qr + 8, N - 1);
        const unsigned* A0 = (const unsigned*)(g_aggh + (size_t)n0 * FT) + qc;
        const unsigned* A1 = (const unsigned*)(g_aggh + (size_t)n1 * FT) + qc;

        float H[4][4], acc[4][4];
        #pragma unroll
        for (int j = 0; j < 4; j++)
            #pragma unroll
            for (int i = 0; i < 4; i++) { H[j][i] = 0.0f; acc[j][i] = 0.0f; }

        #pragma unroll 1
        for (int t = 0; t < TT; t++) {
            float p = sp[t];
            unsigned af[4];
            af[0] = A0[t * 8];     af[1] = A1[t * 8];
            af[2] = A0[t * 8 + 4]; af[3] = A1[t * 8 + 4];

            unsigned hA1[4] = { h2pack(H[0][0], H[0][1]), h2pack(H[0][2], H[0][3]),
                                h2pack(H[1][0], H[1][1]), h2pack(H[1][2], H[1][3]) };
            unsigned hA2[4] = { h2pack(H[2][0], H[2][1]), h2pack(H[2][2], H[2][3]),
                                h2pack(H[3][0], H[3][1]), h2pack(H[3][2], H[3][3]) };

            // ---- z,r GEMM ----
            float Czr[8][4];
            #pragma unroll
            for (int j = 0; j < 8; j++) {
                Czr[j][0] = bzc[j][0]; Czr[j][1] = bzc[j][1];
                Czr[j][2] = bzc[j][0]; Czr[j][3] = bzc[j][1];
            }
            #pragma unroll
            for (int j = 0; j < 8; j++) {
                mma16816(Czr[j], af,  bzr[0][j]);
                mma16816(Czr[j], hA1, bzr[1][j]);
                mma16816(Czr[j], hA2, bzr[2][j]);
            }
            float Z[4][4], R[4][4];
            #pragma unroll
            for (int j = 0; j < 4; j++)
                #pragma unroll
                for (int i = 0; i < 4; i++) {
                    Z[j][i] = sigapx(Czr[j][i]);
                    R[j][i] = sigapx(Czr[4 + j][i]) * H[j][i];
                }

            // ---- candidate GEMM ----
            unsigned rA1[4] = { h2pack(R[0][0], R[0][1]), h2pack(R[0][2], R[0][3]),
                                h2pack(R[1][0], R[1][1]), h2pack(R[1][2], R[1][3]) };
            unsigned rA2[4] = { h2pack(R[2][0], R[2][1]), h2pack(R[2][2], R[2][3]),
                                h2pack(R[3][0], R[3][1]), h2pack(R[3][2], R[3][3]) };
            float Ch[4][4];
            #pragma unroll
            for (int j = 0; j < 4; j++) {
                Ch[j][0] = bhc[j][0]; Ch[j][1] = bhc[j][1];
                Ch[j][2] = bhc[j][0]; Ch[j][3] = bhc[j][1];
            }
            #pragma unroll
            for (int j = 0; j < 4; j++) {
                mma16816(Ch[j], af,  bh[0][j]);
                mma16816(Ch[j], rA1, bh[1][j]);
                mma16816(Ch[j], rA2, bh[2][j]);
            }
            // ---- state update ----
            #pragma unroll
            for (int j = 0; j < 4; j++)
                #pragma unroll
                for (int i = 0; i < 4; i++) {
                    float ht = tanhapx(Ch[j][i]);
                    float z = Z[j][i];
                    H[j][i] = z * H[j][i] + (1.0f - z) * ht;
                    acc[j][i] = fmaf(p, H[j][i], acc[j][i]);
                }
        }

        // ---- relu + reduce ----
        bool v0 = (base + qr)     < N;
        bool v1 = (base + qr + 8) < N;
        #pragma unroll
        for (int j = 0; j < 4; j++) {
            float a0 = acc[j][0], a1 = acc[j][1], a2 = acc[j][2], a3 = acc[j][3];
            float s0 = (v0 ? fmaxf(a0, 0.0f) : 0.0f) + (v1 ? fmaxf(a2, 0.0f) : 0.0f);
            float s1 = (v0 ? fmaxf(a1, 0.0f) : 0.0f) + (v1 ? fmaxf(a3, 0.0f) : 0.0f);
            #pragma unroll
            for (int o = 4; o < 32; o <<= 1) {
                s0 += __shfl_xor_sync(0xffffffffu, s0, o);
                s1 += __shfl_xor_sync(0xffffffffu, s1, o);
            }
            if (qr == 0) {
                atomicAdd(&bsum[8 * j + 2 * qc],     s0);
                atomicAdd(&bsum[8 * j + 2 * qc + 1], s1);
            }
        }
    }
    __syncthreads();
    if (tid < HID) atomicAdd(&g_hsum[tid], bsum[tid]);
}

// Final readout; also re-zeros g_hsum for the next replay.
__global__ void k_final(const float* __restrict__ linW, const float* __restrict__ linb,
                        float* out, int N) {
    int j = threadIdx.x;   // 32 threads
    float invN = 1.0f / (float)N;
    float h = g_hsum[j];
    g_hsum[j] = 0.0f;
    float v = h * invN * linW[j];
    #pragma unroll
    for (int o = 16; o; o >>= 1) v += __shfl_xor_sync(0xffffffffu, v, o);
    if (j == 0) {
        float r = v + linb[0];
        out[0] = r > 0.0f ? r : 0.0f;
    }
}

// ---------------- launcher ----------------
extern "C" void kernel_launch(void* const* d_in, const int* in_sizes, int n_in,
                              void* d_out, int out_size) {
    const float* x    = (const float*)d_in[0];
    const int*   ei   = (const int*)  d_in[1];
    const float* att  = (const float*)d_in[2];
    const float* Wz   = (const float*)d_in[3];
    const float* bz   = (const float*)d_in[4];
    const float* Wr   = (const float*)d_in[5];
    const float* br   = (const float*)d_in[6];
    const float* Wh   = (const float*)d_in[7];
    const float* bh   = (const float*)d_in[8];
    const float* LzW  = (const float*)d_in[9];
    const float* Lzb  = (const float*)d_in[10];
    const float* LrW  = (const float*)d_in[11];
    const float* Lrb  = (const float*)d_in[12];
    const float* LhW  = (const float*)d_in[13];
    const float* Lhb  = (const float*)d_in[14];
    const float* linW = (const float*)d_in[15];
    const float* linb = (const float*)d_in[16];

    int N = in_sizes[0] / FT;
    int E = in_sizes[1] / 2;
    int NB = (N + SB - 1) / SB;
    int NW = (N + 15) / 16;             // gru warps (16 nodes each)
    int NF = (E + 3) / 4;               // fill threads (4 edges each)

    k_pre<<<(N + 3) / 4, 256>>>(x, ei, Wz, bz, Wr, br, Wh, bh,
                                LzW, Lzb, LrW, Lrb, LhW, Lhb, att, N, E);
    k_scan_a<<<NB, SB>>>(N);
    k_scan_c<<<NB, SB>>>(N, E, NB);
    k_fill<<<(NF + 255) / 256, 256>>>(ei, E, N);
    k_gather<<<(N * 32 + 255) / 256, 256>>>(N);
    k_gru<<<(NW + 3) / 4, 128>>>(LzW, LrW, LhW, N);
    k_final<<<1, 32>>>(linW, linb, (float*)d_out, N);
}